// round 3
// baseline (speedup 1.0000x reference)
#include <cuda_runtime.h>

// ---------------- problem constants (fixed by setup_inputs) ----------------
#define NNODE 50000
#define NEDGE 800000
#define NFEAT 500
#define NHID  64
#define NH    4
#define NHC   16
#define NC    8
#define MPN   512          // H*HC*C per-node M size
#define CSTF  1e-5f

// ---------------- device scratch (no runtime allocation allowed) ----------
__device__ float g_x   [NNODE * NHID];
__device__ float g_Q   [NNODE * NHID];
__device__ float g_Kf  [NNODE * NHID];
__device__ float g_V   [NNODE * NH * NC];
__device__ float g_M1  [NNODE * MPN];          // 102.4 MB
__device__ float g_K1  [NNODE * NHID];
__device__ float g_Hh1 [NNODE * 32];
__device__ float g_Cc1 [NNODE * NH];
__device__ int   g_row [NEDGE];
__device__ int   g_col [NEDGE];
__device__ int   g_deg [NNODE];
__device__ float g_dinv[NNODE];
__device__ int   g_rowptr[NNODE + 1];
__device__ int   g_cursor[NNODE];
__device__ int   g_srcs[NEDGE];
__device__ float g_wts [NEDGE];
__device__ float g_TM  [MPN];                   // sum_n Kf(h,i)*V(h,j), layout i*32+h*8+j
__device__ float g_TK  [NHID];                  // sum_n Kf
__device__ float g_coef[16];                    // [0]=hop0 [1]=teleport [2+h]=g1[h] [6+h]=g2[h]
__device__ int   g_is64;

// ---------------- edge dtype detection + normalization --------------------
// If edge_index is int64 with values < 2^31, every odd int32 word of the first
// 256 words is 0 (little-endian high halves). If it's int32 random data in
// [0, 50000), that's essentially impossible.
__global__ void k_detect(const int* __restrict__ ei32) {
    if (threadIdx.x != 0 || blockIdx.x != 0) return;
    int all0 = 1;
    for (int i = 1; i < 256; i += 2)
        if (ei32[i] != 0) { all0 = 0; break; }
    g_is64 = all0;
}

__global__ void k_edges(const void* __restrict__ eiraw) {
    int e = blockIdx.x * blockDim.x + threadIdx.x;
    if (e >= NEDGE) return;
    int r, c;
    if (g_is64) {
        const long long* p = (const long long*)eiraw;
        r = (int)p[e];
        c = (int)p[NEDGE + e];
    } else {
        const int* p = (const int*)eiraw;
        r = p[e];
        c = p[NEDGE + e];
    }
    // defensive clamp: guarantees no OOB downstream regardless of input dtype
    r = min(max(r, 0), NNODE - 1);
    c = min(max(c, 0), NNODE - 1);
    g_row[e] = r;
    g_col[e] = c;
}

// ---------------- small helpers ----------------
__global__ void k_zero() {
    int i = blockIdx.x * blockDim.x + threadIdx.x;
    if (i < NNODE) g_deg[i] = 0;
    if (i < MPN)   g_TM[i] = 0.f;
    if (i < NHID)  g_TK[i] = 0.f;
}

__global__ void k_deg() {
    int e = blockIdx.x * blockDim.x + threadIdx.x;
    if (e >= NEDGE) return;
    atomicAdd(&g_deg[g_col[e]], 1);
}

// single-block scan: rowptr, cursor, deg_inv
__global__ void k_scan() {
    __shared__ int ssum[1024];
    const int CH = (NNODE + 1023) / 1024;   // 49
    int t = threadIdx.x;
    int beg = t * CH;
    int end = beg + CH; if (end > NNODE) end = NNODE;
    int s = 0;
    for (int i = beg; i < end; i++) s += g_deg[i];
    ssum[t] = s;
    __syncthreads();
    for (int off = 1; off < 1024; off <<= 1) {
        int v = 0;
        if (t >= off) v = ssum[t - off];
        __syncthreads();
        ssum[t] += v;
        __syncthreads();
    }
    int run = ssum[t] - s;    // exclusive prefix
    for (int i = beg; i < end; i++) {
        g_rowptr[i] = run;
        g_cursor[i] = run;
        int d = g_deg[i];
        g_dinv[i] = (d > 0) ? (1.0f / (float)d) : 0.0f;
        run += d;
    }
    if (t == 0) g_rowptr[NNODE] = NEDGE;
}

__global__ void k_scatter() {
    int e = blockIdx.x * blockDim.x + threadIdx.x;
    if (e >= NEDGE) return;
    int r = g_row[e];
    int c = g_col[e];
    int pos = atomicAdd(&g_cursor[c], 1);
    g_srcs[pos] = r;
    g_wts[pos]  = g_dinv[r];
}

__global__ void k_coef(const float* __restrict__ hopwise,
                       const float* __restrict__ headwise,
                       const float* __restrict__ teleport) {
    if (threadIdx.x != 0 || blockIdx.x != 0) return;
    g_coef[0] = hopwise[0];
    g_coef[1] = teleport[0];
    for (int hop = 0; hop < 2; hop++) {
        float m = -1e30f;
        for (int h = 0; h < NH; h++) { float v = headwise[h * 2 + hop]; if (v > m) m = v; }
        float ex[NH]; float sum = 0.f;
        for (int h = 0; h < NH; h++) { ex[h] = expf(headwise[h * 2 + hop] - m); sum += ex[h]; }
        for (int h = 0; h < NH; h++)
            g_coef[2 + hop * 4 + h] = hopwise[hop + 1] * ex[h] / sum;
    }
}

// ---------------- GEMM1: x = relu(feat @ Wi + bi), [N,500]x[500,64] -------
__global__ void k_gemm_x(const float* __restrict__ feat,
                         const float* __restrict__ Wi,
                         const float* __restrict__ bi) {
    __shared__ float sA[32][68];   // [kk][m]
    __shared__ float sB[32][64];   // [kk][c]
    int bm  = blockIdx.x * 64;
    int tid = threadIdx.x;
    int tx  = tid & 15, ty = tid >> 4;
    float acc[4][4];
#pragma unroll
    for (int i = 0; i < 4; i++)
#pragma unroll
        for (int j = 0; j < 4; j++) acc[i][j] = 0.f;

    for (int k0 = 0; k0 < NFEAT; k0 += 32) {
#pragma unroll
        for (int i = 0; i < 8; i++) {
            int idx = tid + i * 256;
            int m = idx >> 5, kk = idx & 31;
            int row = bm + m, kg = k0 + kk;
            sA[kk][m] = (row < NNODE && kg < NFEAT) ? feat[(long)row * NFEAT + kg] : 0.f;
        }
#pragma unroll
        for (int i = 0; i < 8; i++) {
            int idx = tid + i * 256;
            int kk = idx >> 6, c = idx & 63;
            int kg = k0 + kk;
            sB[kk][c] = (kg < NFEAT) ? Wi[kg * 64 + c] : 0.f;
        }
        __syncthreads();
#pragma unroll
        for (int kk = 0; kk < 32; kk++) {
            float a[4], b[4];
#pragma unroll
            for (int i = 0; i < 4; i++) a[i] = sA[kk][ty * 4 + i];
#pragma unroll
            for (int j = 0; j < 4; j++) b[j] = sB[kk][tx * 4 + j];
#pragma unroll
            for (int i = 0; i < 4; i++)
#pragma unroll
                for (int j = 0; j < 4; j++) acc[i][j] += a[i] * b[j];
        }
        __syncthreads();
    }
#pragma unroll
    for (int i = 0; i < 4; i++) {
        int row = bm + ty * 4 + i;
        if (row >= NNODE) continue;
#pragma unroll
        for (int j = 0; j < 4; j++) {
            int c = tx * 4 + j;
            float v = acc[i][j] + bi[c];
            g_x[row * 64 + c] = v > 0.f ? v : 0.f;
        }
    }
}

// ---------------- QKV: [N,64] x [64,160] -> Q(1+elu), K(1+elu), V --------
__global__ void k_qkv(const float* __restrict__ Wq, const float* __restrict__ bq,
                      const float* __restrict__ Wk, const float* __restrict__ bk,
                      const float* __restrict__ Wv, const float* __restrict__ bv) {
    __shared__ float sX[32][68];     // [kk][m]
    __shared__ float sW[32][160];    // [kk][c]
    int bm  = blockIdx.x * 64;
    int tid = threadIdx.x;
    int tx  = tid & 15, ty = tid >> 4;
    float acc[4][10];
#pragma unroll
    for (int i = 0; i < 4; i++)
#pragma unroll
        for (int j = 0; j < 10; j++) acc[i][j] = 0.f;

    for (int k0 = 0; k0 < 64; k0 += 32) {
#pragma unroll
        for (int i = 0; i < 8; i++) {
            int idx = tid + i * 256;
            int m = idx >> 5, kk = idx & 31;
            int row = bm + m;
            sX[kk][m] = (row < NNODE) ? g_x[row * 64 + k0 + kk] : 0.f;
        }
#pragma unroll
        for (int i = 0; i < 20; i++) {
            int idx = tid + i * 256;
            int kk = idx / 160, c = idx % 160;
            int kg = k0 + kk;
            float v;
            if (c < 64)       v = Wq[kg * 64 + c];
            else if (c < 128) v = Wk[kg * 64 + (c - 64)];
            else              v = Wv[kg * 32 + (c - 128)];
            sW[kk][c] = v;
        }
        __syncthreads();
#pragma unroll
        for (int kk = 0; kk < 32; kk++) {
            float a[4];
#pragma unroll
            for (int i = 0; i < 4; i++) a[i] = sX[kk][ty * 4 + i];
#pragma unroll
            for (int j = 0; j < 10; j++) {
                float b = sW[kk][tx * 10 + j];
#pragma unroll
                for (int i = 0; i < 4; i++) acc[i][j] += a[i] * b;
            }
        }
        __syncthreads();
    }
#pragma unroll
    for (int i = 0; i < 4; i++) {
        int row = bm + ty * 4 + i;
        if (row >= NNODE) continue;
#pragma unroll
        for (int j = 0; j < 10; j++) {
            int c = tx * 10 + j;
            float v = acc[i][j];
            if (c < 64) {
                v += bq[c];
                v = v > 0.f ? 1.f + v : expf(v);     // 1+elu
                g_Q[row * 64 + c] = v;
            } else if (c < 128) {
                v += bk[c - 64];
                v = v > 0.f ? 1.f + v : expf(v);
                g_Kf[row * 64 + (c - 64)] = v;
            } else {
                v += bv[c - 128];
                g_V[row * 32 + (c - 128)] = v;
            }
        }
    }
}

// ---------------- teleport reductions: TM = sum Kf(h,i)*V(h,j), TK = sum Kf
__global__ void k_tmtk() {
    __shared__ float sK[64 * 64];
    __shared__ float sV[64 * 32];
    int base = blockIdx.x * 64;
    int tid  = threadIdx.x;
#pragma unroll
    for (int i = 0; i < 16; i++) {
        int idx = tid + i * 256;       // 4096 elems
        int r = idx >> 6, c = idx & 63;
        int row = base + r;
        sK[idx] = (row < NNODE) ? g_Kf[row * 64 + c] : 0.f;
    }
#pragma unroll
    for (int i = 0; i < 8; i++) {
        int idx = tid + i * 256;       // 2048 elems
        int r = idx >> 5, c = idx & 31;
        int row = base + r;
        sV[idx] = (row < NNODE) ? g_V[row * 32 + c] : 0.f;
    }
    __syncthreads();
    // thread owns TM entries 2t and 2t+1 ; entry = i*32 + h*8 + j
    int e0 = 2 * tid;
    int i_  = e0 >> 5;
    int p   = e0 & 31;
    int kidx = (p >> 3) * 16 + i_;
    float a0 = 0.f, a1 = 0.f;
#pragma unroll 8
    for (int r = 0; r < 64; r++) {
        float kf = sK[r * 64 + kidx];
        a0 += kf * sV[r * 32 + p];
        a1 += kf * sV[r * 32 + p + 1];
    }
    atomicAdd(&g_TM[e0], a0);
    atomicAdd(&g_TM[e0 + 1], a1);
    if (tid < 64) {
        float s = 0.f;
#pragma unroll 8
        for (int r = 0; r < 64; r++) s += sK[r * 64 + tid];
        atomicAdd(&g_TK[tid], s);
    }
}

// ---------------- hop1: warp per destination node --------------------------
// builds M1[n] (layout n*512 + i*32 + (h*8+j)), K1[n], Hh1[n], Cc1[n]
__global__ void k_hop1() {
    int w = (blockIdx.x * blockDim.x + threadIdx.x) >> 5;
    int l = threadIdx.x & 31;
    if (w >= NNODE) return;
    int n = w;
    int h = l >> 3;
    int grp = l & 24;

    float q[16];
    {
        const float4* qp = reinterpret_cast<const float4*>(&g_Q[n * 64 + h * 16]);
        float4 a = qp[0], b = qp[1], c = qp[2], d = qp[3];
        q[0]=a.x; q[1]=a.y; q[2]=a.z; q[3]=a.w;
        q[4]=b.x; q[5]=b.y; q[6]=b.z; q[7]=b.w;
        q[8]=c.x; q[9]=c.y; q[10]=c.z; q[11]=c.w;
        q[12]=d.x; q[13]=d.y; q[14]=d.z; q[15]=d.w;
    }
    float macc[16];
#pragma unroll
    for (int i = 0; i < 16; i++) macc[i] = 0.f;
    float kf1a = 0.f, kf1b = 0.f, hh = 0.f;

    int e0 = g_rowptr[n], e1 = g_rowptr[n + 1];
    for (int e = e0; e < e1; e++) {
        int src   = g_srcs[e];
        float wgt = g_wts[e];
        float2 kf = *reinterpret_cast<const float2*>(&g_Kf[src * 64 + 2 * l]);
        float vv  = g_V[src * 32 + l];
        kf1a += wgt * kf.x;
        kf1b += wgt * kf.y;
        float s = 0.f;
        float wv = wgt * vv;
#pragma unroll
        for (int i = 0; i < 16; i++) {
            float kfi = __shfl_sync(0xffffffffu, (i & 1) ? kf.y : kf.x, grp + (i >> 1));
            macc[i] += wv * kfi;
            s += q[i] * kfi;
        }
        hh += wgt * s * vv;
    }
    float* mp = &g_M1[n * MPN + l];
#pragma unroll
    for (int i = 0; i < 16; i++) mp[i * 32] = macc[i];
    *reinterpret_cast<float2*>(&g_K1[n * 64 + 2 * l]) = make_float2(kf1a, kf1b);
    g_Hh1[n * 32 + l] = hh;
    // Cc1
    int m8 = l & 7;
    float p = q[2 * m8] * kf1a + q[2 * m8 + 1] * kf1b;
    p += __shfl_xor_sync(0xffffffffu, p, 1);
    p += __shfl_xor_sync(0xffffffffu, p, 2);
    p += __shfl_xor_sync(0xffffffffu, p, 4);
    if (m8 == 0) g_Cc1[n * 4 + h] = p + CSTF;
}

// ---------------- hop2 + teleport + output projection ----------------------
__global__ void k_hop2(const float* __restrict__ Wo,
                       const float* __restrict__ bo,
                       float* __restrict__ out) {
    int w = (blockIdx.x * blockDim.x + threadIdx.x) >> 5;
    int l = threadIdx.x & 31;
    if (w >= NNODE) return;
    int n = w;
    int h = l >> 3;

    float q[16];
    {
        const float4* qp = reinterpret_cast<const float4*>(&g_Q[n * 64 + h * 16]);
        float4 a = qp[0], b = qp[1], c = qp[2], d = qp[3];
        q[0]=a.x; q[1]=a.y; q[2]=a.z; q[3]=a.w;
        q[4]=b.x; q[5]=b.y; q[6]=b.z; q[7]=b.w;
        q[8]=c.x; q[9]=c.y; q[10]=c.z; q[11]=c.w;
        q[12]=d.x; q[13]=d.y; q[14]=d.z; q[15]=d.w;
    }
    float acc2 = 0.f, k2a = 0.f, k2b = 0.f;
    int e0 = g_rowptr[n], e1 = g_rowptr[n + 1];
    for (int e = e0; e < e1; e++) {
        int src   = g_srcs[e];
        float wgt = g_wts[e];
        const float* mp = &g_M1[src * MPN + l];
        float t = 0.f;
#pragma unroll
        for (int i = 0; i < 16; i++) t += q[i] * mp[i * 32];
        acc2 += wgt * t;
        float2 k1 = *reinterpret_cast<const float2*>(&g_K1[src * 64 + 2 * l]);
        k2a += wgt * k1.x;
        k2b += wgt * k1.y;
    }
    // Cc2
    int m8 = l & 7;
    float p = q[2 * m8] * k2a + q[2 * m8 + 1] * k2b;
    p += __shfl_xor_sync(0xffffffffu, p, 1);
    p += __shfl_xor_sync(0xffffffffu, p, 2);
    p += __shfl_xor_sync(0xffffffffu, p, 4);
    float cc2 = p + CSTF;
    float cc1 = g_Cc1[n * 4 + h];

    float hop0 = g_coef[0], tele = g_coef[1];
    float g1 = g_coef[2 + h], g2 = g_coef[6 + h];
    float hidden = g_V[n * 32 + l] * hop0
                 + g1 * g_Hh1[n * 32 + l] / cc1
                 + g2 * acc2 / cc2;

    // teleport term
    const float invN = 1.0f / (float)NNODE;
    float num = 0.f, den = 0.f;
#pragma unroll
    for (int i = 0; i < 16; i++) {
        num += q[i] * g_TM[i * 32 + l];
        den += q[i] * g_TK[h * 16 + i];
    }
    float th = (num * invN) / (den * invN + CSTF);
    th += __shfl_xor_sync(0xffffffffu, th, 8);
    th += __shfl_xor_sync(0xffffffffu, th, 16);   // sum over heads; lanes with same j hold TH[j]

    // output: out[c] = sum_l hidden_l * Wo[l][c] + bo[c] + tele*TH[c]
    float wo[8];
#pragma unroll
    for (int c = 0; c < 8; c++) wo[c] = Wo[l * 8 + c];
    float res = 0.f;
#pragma unroll
    for (int c = 0; c < 8; c++) {
        float v = hidden * wo[c];
        v += __shfl_xor_sync(0xffffffffu, v, 16);
        v += __shfl_xor_sync(0xffffffffu, v, 8);
        v += __shfl_xor_sync(0xffffffffu, v, 4);
        v += __shfl_xor_sync(0xffffffffu, v, 2);
        v += __shfl_xor_sync(0xffffffffu, v, 1);
        if (l == c) res = v;
    }
    if (l < 8) out[n * 8 + l] = res + bo[l] + tele * th;
}

// ---------------- launch ---------------------------------------------------
extern "C" void kernel_launch(void* const* d_in, const int* in_sizes, int n_in,
                              void* d_out, int out_size) {
    const float*     feat = (const float*)d_in[0];
    const void*      ei   = d_in[1];
    const float*     Wi   = (const float*)d_in[2];
    const float*     bi   = (const float*)d_in[3];
    const float*     Wq   = (const float*)d_in[4];
    const float*     bq   = (const float*)d_in[5];
    const float*     Wk   = (const float*)d_in[6];
    const float*     bk   = (const float*)d_in[7];
    const float*     Wv   = (const float*)d_in[8];
    const float*     bv   = (const float*)d_in[9];
    const float*     Wo   = (const float*)d_in[10];
    const float*     bo   = (const float*)d_in[11];
    const float*     hopw = (const float*)d_in[12];
    const float*     headw= (const float*)d_in[13];
    const float*     tel  = (const float*)d_in[14];
    float* out = (float*)d_out;

    k_detect<<<1, 32>>>((const int*)ei);
    k_edges<<<(NEDGE + 255) / 256, 256>>>(ei);
    k_zero<<<(NNODE + 255) / 256, 256>>>();
    k_deg<<<(NEDGE + 255) / 256, 256>>>();
    k_scan<<<1, 1024>>>();
    k_scatter<<<(NEDGE + 255) / 256, 256>>>();
    k_coef<<<1, 32>>>(hopw, headw, tel);
    k_gemm_x<<<(NNODE + 63) / 64, 256>>>(feat, Wi, bi);
    k_qkv<<<(NNODE + 63) / 64, 256>>>(Wq, bq, Wk, bk, Wv, bv);
    k_tmtk<<<(NNODE + 63) / 64, 256>>>();
    k_hop1<<<(NNODE * 32 + 255) / 256, 256>>>();
    k_hop2<<<(NNODE * 32 + 255) / 256, 256>>>(Wo, bo, out);
}

// round 5
// speedup vs baseline: 1.2264x; 1.2264x over previous
#include <cuda_runtime.h>
#include <cuda_fp16.h>

// ---------------- problem constants ----------------
#define NNODE 50000
#define NEDGE 800000
#define NFEAT 500
#define NHID  64
#define NH    4
#define NHC   16
#define NC    8
#define MPN   512
#define CSTF  1e-5f

// ---------------- device scratch ----------------
__device__ float   g_x   [NNODE * NHID];
__device__ float   g_Q   [NNODE * NHID];
__device__ float   g_Kf  [NNODE * NHID];
__device__ float   g_V   [NNODE * NH * NC];
__device__ __half2 g_M1h [NNODE * 256];        // 51.2 MB, pairs (i=2ip, i=2ip+1) at [n*256+ip*32+l]
__device__ float   g_K1  [NNODE * NHID];
__device__ float   g_Hh1 [NNODE * 32];
__device__ float   g_Cc1 [NNODE * NH];
__device__ int     g_row [NEDGE];
__device__ int     g_col [NEDGE];
__device__ int     g_deg [NNODE];
__device__ float   g_dinv[NNODE];
__device__ int     g_rowptr[NNODE + 1];
__device__ int     g_cursor[NNODE];
__device__ int     g_srcs[NEDGE];
__device__ float   g_wts [NEDGE];
__device__ float   g_TM  [MPN];
__device__ float   g_TK  [NHID];
__device__ float   g_coef[16];
__device__ int     g_is64;

// ---------------- edge dtype detection + normalization --------------------
__global__ void k_detect(const int* __restrict__ ei32) {
    __shared__ int s;
    int t = threadIdx.x;
    if (t == 0) s = 1;
    __syncthreads();
    if (ei32[2 * t + 1] != 0) s = 0;   // benign race: any writer writes 0
    __syncthreads();
    if (t == 0) g_is64 = s;
}

__global__ void k_edges(const void* __restrict__ eiraw) {
    int e = blockIdx.x * blockDim.x + threadIdx.x;
    if (e >= NEDGE) return;
    int r, c;
    if (g_is64) {
        const long long* p = (const long long*)eiraw;
        r = (int)p[e];
        c = (int)p[NEDGE + e];
    } else {
        const int* p = (const int*)eiraw;
        r = p[e];
        c = p[NEDGE + e];
    }
    r = min(max(r, 0), NNODE - 1);
    c = min(max(c, 0), NNODE - 1);
    g_row[e] = r;
    g_col[e] = c;
}

// ---------------- small helpers ----------------
__global__ void k_zero() {
    int i = blockIdx.x * blockDim.x + threadIdx.x;
    if (i < NNODE) g_deg[i] = 0;
    if (i < MPN)   g_TM[i] = 0.f;
    if (i < NHID)  g_TK[i] = 0.f;
}

__global__ void k_deg() {
    int e = blockIdx.x * blockDim.x + threadIdx.x;
    if (e >= NEDGE) return;
    atomicAdd(&g_deg[g_col[e]], 1);
}

__global__ void k_scan() {
    __shared__ int ssum[1024];
    const int CH = (NNODE + 1023) / 1024;
    int t = threadIdx.x;
    int beg = t * CH;
    int end = beg + CH; if (end > NNODE) end = NNODE;
    int s = 0;
    for (int i = beg; i < end; i++) s += g_deg[i];
    ssum[t] = s;
    __syncthreads();
    for (int off = 1; off < 1024; off <<= 1) {
        int v = 0;
        if (t >= off) v = ssum[t - off];
        __syncthreads();
        ssum[t] += v;
        __syncthreads();
    }
    int run = ssum[t] - s;
    for (int i = beg; i < end; i++) {
        g_rowptr[i] = run;
        g_cursor[i] = run;
        int d = g_deg[i];
        g_dinv[i] = (d > 0) ? (1.0f / (float)d) : 0.0f;
        run += d;
    }
    if (t == 0) g_rowptr[NNODE] = NEDGE;
}

__global__ void k_scatter() {
    int e = blockIdx.x * blockDim.x + threadIdx.x;
    if (e >= NEDGE) return;
    int r = g_row[e];
    int c = g_col[e];
    int pos = atomicAdd(&g_cursor[c], 1);
    g_srcs[pos] = r;
    g_wts[pos]  = g_dinv[r];
}

__global__ void k_coef(const float* __restrict__ hopwise,
                       const float* __restrict__ headwise,
                       const float* __restrict__ teleport) {
    if (threadIdx.x != 0 || blockIdx.x != 0) return;
    g_coef[0] = hopwise[0];
    g_coef[1] = teleport[0];
    for (int hop = 0; hop < 2; hop++) {
        float m = -1e30f;
        for (int h = 0; h < NH; h++) { float v = headwise[h * 2 + hop]; if (v > m) m = v; }
        float ex[NH]; float sum = 0.f;
        for (int h = 0; h < NH; h++) { ex[h] = expf(headwise[h * 2 + hop] - m); sum += ex[h]; }
        for (int h = 0; h < NH; h++)
            g_coef[2 + hop * 4 + h] = hopwise[hop + 1] * ex[h] / sum;
    }
}

// ---------------- GEMM1: x = relu(feat @ Wi + bi) --------------------------
// 128x64 tile, 256 threads, 8x4 micro-tile, BK=16
#define AS 132
__global__ void __launch_bounds__(256, 2) k_gemm_x(const float* __restrict__ feat,
                         const float* __restrict__ Wi,
                         const float* __restrict__ bi) {
    __shared__ float sA[16 * AS];    // [k][m], padded
    __shared__ float sB[16 * 64];    // [k][c]
    int bm  = blockIdx.x * 128;
    int tid = threadIdx.x;
    int tx  = tid & 15;              // n: 16*4 = 64
    int ty  = tid >> 4;              // m: 16*8 = 128

    float acc[8][4];
#pragma unroll
    for (int i = 0; i < 8; i++)
#pragma unroll
        for (int j = 0; j < 4; j++) acc[i][j] = 0.f;

    for (int k0 = 0; k0 < NFEAT; k0 += 16) {
        // load A tile: 128 rows x 16 k = 512 float4
#pragma unroll
        for (int i = 0; i < 2; i++) {
            int f   = tid + i * 256;
            int row = f >> 2;
            int kq  = f & 3;
            int gk  = k0 + kq * 4;
            int grow = bm + row;
            float4 v = make_float4(0.f, 0.f, 0.f, 0.f);
            if (grow < NNODE && gk < NFEAT)
                v = *reinterpret_cast<const float4*>(&feat[(long)grow * NFEAT + gk]);
            sA[(kq * 4 + 0) * AS + row] = v.x;
            sA[(kq * 4 + 1) * AS + row] = v.y;
            sA[(kq * 4 + 2) * AS + row] = v.z;
            sA[(kq * 4 + 3) * AS + row] = v.w;
        }
        // load B tile: 16 k x 64 c = 256 float4
        {
            int kk = tid >> 4;
            int c  = (tid & 15) * 4;
            int gk = k0 + kk;
            float4 v = make_float4(0.f, 0.f, 0.f, 0.f);
            if (gk < NFEAT)
                v = *reinterpret_cast<const float4*>(&Wi[gk * 64 + c]);
            *reinterpret_cast<float4*>(&sB[kk * 64 + c]) = v;
        }
        __syncthreads();
#pragma unroll
        for (int kk = 0; kk < 16; kk++) {
            float a[8], b[4];
            *reinterpret_cast<float4*>(&a[0]) = *reinterpret_cast<const float4*>(&sA[kk * AS + ty * 8]);
            *reinterpret_cast<float4*>(&a[4]) = *reinterpret_cast<const float4*>(&sA[kk * AS + ty * 8 + 4]);
            *reinterpret_cast<float4*>(&b[0]) = *reinterpret_cast<const float4*>(&sB[kk * 64 + tx * 4]);
#pragma unroll
            for (int i = 0; i < 8; i++)
#pragma unroll
                for (int j = 0; j < 4; j++) acc[i][j] += a[i] * b[j];
        }
        __syncthreads();
    }
    float bb[4];
    *reinterpret_cast<float4*>(&bb[0]) = *reinterpret_cast<const float4*>(&bi[tx * 4]);
#pragma unroll
    for (int i = 0; i < 8; i++) {
        int grow = bm + ty * 8 + i;
        if (grow >= NNODE) continue;
        float4 o;
        o.x = fmaxf(acc[i][0] + bb[0], 0.f);
        o.y = fmaxf(acc[i][1] + bb[1], 0.f);
        o.z = fmaxf(acc[i][2] + bb[2], 0.f);
        o.w = fmaxf(acc[i][3] + bb[3], 0.f);
        *reinterpret_cast<float4*>(&g_x[grow * 64 + tx * 4]) = o;
    }
}

// ---------------- QKV: [N,64] x [64,160] -> Q(1+elu), K(1+elu), V ---------
__global__ void k_qkv(const float* __restrict__ Wq, const float* __restrict__ bq,
                      const float* __restrict__ Wk, const float* __restrict__ bk,
                      const float* __restrict__ Wv, const float* __restrict__ bv) {
    __shared__ float sX[32][68];
    __shared__ float sW[32][160];
    int bm  = blockIdx.x * 64;
    int tid = threadIdx.x;
    int tx  = tid & 15, ty = tid >> 4;
    float acc[4][10];
#pragma unroll
    for (int i = 0; i < 4; i++)
#pragma unroll
        for (int j = 0; j < 10; j++) acc[i][j] = 0.f;

    for (int k0 = 0; k0 < 64; k0 += 32) {
#pragma unroll
        for (int i = 0; i < 8; i++) {
            int idx = tid + i * 256;
            int m = idx >> 5, kk = idx & 31;
            int row = bm + m;
            sX[kk][m] = (row < NNODE) ? g_x[row * 64 + k0 + kk] : 0.f;
        }
#pragma unroll
        for (int i = 0; i < 20; i++) {
            int idx = tid + i * 256;
            int kk = idx / 160, c = idx % 160;
            int kg = k0 + kk;
            float v;
            if (c < 64)       v = Wq[kg * 64 + c];
            else if (c < 128) v = Wk[kg * 64 + (c - 64)];
            else              v = Wv[kg * 32 + (c - 128)];
            sW[kk][c] = v;
        }
        __syncthreads();
#pragma unroll
        for (int kk = 0; kk < 32; kk++) {
            float a[4];
#pragma unroll
            for (int i = 0; i < 4; i++) a[i] = sX[kk][ty * 4 + i];
#pragma unroll
            for (int j = 0; j < 10; j++) {
                float b = sW[kk][tx * 10 + j];
#pragma unroll
                for (int i = 0; i < 4; i++) acc[i][j] += a[i] * b;
            }
        }
        __syncthreads();
    }
#pragma unroll
    for (int i = 0; i < 4; i++) {
        int row = bm + ty * 4 + i;
        if (row >= NNODE) continue;
#pragma unroll
        for (int j = 0; j < 10; j++) {
            int c = tx * 10 + j;
            float v = acc[i][j];
            if (c < 64) {
                v += bq[c];
                v = v > 0.f ? 1.f + v : expf(v);
                g_Q[row * 64 + c] = v;
            } else if (c < 128) {
                v += bk[c - 64];
                v = v > 0.f ? 1.f + v : expf(v);
                g_Kf[row * 64 + (c - 64)] = v;
            } else {
                v += bv[c - 128];
                g_V[row * 32 + (c - 128)] = v;
            }
        }
    }
}

// ---------------- teleport reductions ----------------
__global__ void k_tmtk() {
    __shared__ float sK[64 * 64];
    __shared__ float sV[64 * 32];
    int base = blockIdx.x * 64;
    int tid  = threadIdx.x;
#pragma unroll
    for (int i = 0; i < 16; i++) {
        int idx = tid + i * 256;
        int r = idx >> 6, c = idx & 63;
        int row = base + r;
        sK[idx] = (row < NNODE) ? g_Kf[row * 64 + c] : 0.f;
    }
#pragma unroll
    for (int i = 0; i < 8; i++) {
        int idx = tid + i * 256;
        int r = idx >> 5, c = idx & 31;
        int row = base + r;
        sV[idx] = (row < NNODE) ? g_V[row * 32 + c] : 0.f;
    }
    __syncthreads();
    int e0 = 2 * tid;
    int i_  = e0 >> 5;
    int p   = e0 & 31;
    int kidx = (p >> 3) * 16 + i_;
    float a0 = 0.f, a1 = 0.f;
#pragma unroll 8
    for (int r = 0; r < 64; r++) {
        float kf = sK[r * 64 + kidx];
        a0 += kf * sV[r * 32 + p];
        a1 += kf * sV[r * 32 + p + 1];
    }
    atomicAdd(&g_TM[e0], a0);
    atomicAdd(&g_TM[e0 + 1], a1);
    if (tid < 64) {
        float s = 0.f;
#pragma unroll 8
        for (int r = 0; r < 64; r++) s += sK[r * 64 + tid];
        atomicAdd(&g_TK[tid], s);
    }
}

// ---------------- hop1: warp per destination node --------------------------
__global__ void k_hop1() {
    int w = (blockIdx.x * blockDim.x + threadIdx.x) >> 5;
    int l = threadIdx.x & 31;
    if (w >= NNODE) return;
    int n = w;
    int h = l >> 3;
    int grp = l & 24;

    float q[16];
    {
        const float4* qp = reinterpret_cast<const float4*>(&g_Q[n * 64 + h * 16]);
        float4 a = qp[0], b = qp[1], c = qp[2], d = qp[3];
        q[0]=a.x; q[1]=a.y; q[2]=a.z; q[3]=a.w;
        q[4]=b.x; q[5]=b.y; q[6]=b.z; q[7]=b.w;
        q[8]=c.x; q[9]=c.y; q[10]=c.z; q[11]=c.w;
        q[12]=d.x; q[13]=d.y; q[14]=d.z; q[15]=d.w;
    }
    float macc[16];
#pragma unroll
    for (int i = 0; i < 16; i++) macc[i] = 0.f;
    float kf1a = 0.f, kf1b = 0.f, hh = 0.f;

    int e0 = g_rowptr[n], e1 = g_rowptr[n + 1];
    for (int e = e0; e < e1; e++) {
        int src   = g_srcs[e];
        float wgt = g_wts[e];
        float2 kf = *reinterpret_cast<const float2*>(&g_Kf[src * 64 + 2 * l]);
        float vv  = g_V[src * 32 + l];
        kf1a += wgt * kf.x;
        kf1b += wgt * kf.y;
        float s = 0.f;
        float wv = wgt * vv;
#pragma unroll
        for (int i = 0; i < 16; i++) {
            float kfi = __shfl_sync(0xffffffffu, (i & 1) ? kf.y : kf.x, grp + (i >> 1));
            macc[i] += wv * kfi;
            s += q[i] * kfi;
        }
        hh += wgt * s * vv;
    }
    // store M1 as half2 pairs: [n*256 + ip*32 + l] = (macc[2ip], macc[2ip+1])
    __half2* mp = &g_M1h[n * 256 + l];
#pragma unroll
    for (int ip = 0; ip < 8; ip++)
        mp[ip * 32] = __floats2half2_rn(macc[2 * ip], macc[2 * ip + 1]);
    *reinterpret_cast<float2*>(&g_K1[n * 64 + 2 * l]) = make_float2(kf1a, kf1b);
    g_Hh1[n * 32 + l] = hh;
    int m8 = l & 7;
    float p = q[2 * m8] * kf1a + q[2 * m8 + 1] * kf1b;
    p += __shfl_xor_sync(0xffffffffu, p, 1);
    p += __shfl_xor_sync(0xffffffffu, p, 2);
    p += __shfl_xor_sync(0xffffffffu, p, 4);
    if (m8 == 0) g_Cc1[n * 4 + h] = p + CSTF;
}

// ---------------- hop2 + teleport + output projection ----------------------
__global__ void k_hop2(const float* __restrict__ Wo,
                       const float* __restrict__ bo,
                       float* __restrict__ out) {
    int w = (blockIdx.x * blockDim.x + threadIdx.x) >> 5;
    int l = threadIdx.x & 31;
    if (w >= NNODE) return;
    int n = w;
    int h = l >> 3;

    float q[16];
    {
        const float4* qp = reinterpret_cast<const float4*>(&g_Q[n * 64 + h * 16]);
        float4 a = qp[0], b = qp[1], c = qp[2], d = qp[3];
        q[0]=a.x; q[1]=a.y; q[2]=a.z; q[3]=a.w;
        q[4]=b.x; q[5]=b.y; q[6]=b.z; q[7]=b.w;
        q[8]=c.x; q[9]=c.y; q[10]=c.z; q[11]=c.w;
        q[12]=d.x; q[13]=d.y; q[14]=d.z; q[15]=d.w;
    }
    float acc2 = 0.f, k2a = 0.f, k2b = 0.f;
    int e0 = g_rowptr[n], e1 = g_rowptr[n + 1];
    for (int e = e0; e < e1; e++) {
        int src   = g_srcs[e];
        float wgt = g_wts[e];
        const __half2* mp = &g_M1h[src * 256 + l];
        float t = 0.f;
#pragma unroll
        for (int ip = 0; ip < 8; ip++) {
            float2 mf = __half22float2(mp[ip * 32]);
            t += q[2 * ip] * mf.x + q[2 * ip + 1] * mf.y;
        }
        acc2 += wgt * t;
        float2 k1 = *reinterpret_cast<const float2*>(&g_K1[src * 64 + 2 * l]);
        k2a += wgt * k1.x;
        k2b += wgt * k1.y;
    }
    int m8 = l & 7;
    float p = q[2 * m8] * k2a + q[2 * m8 + 1] * k2b;
    p += __shfl_xor_sync(0xffffffffu, p, 1);
    p += __shfl_xor_sync(0xffffffffu, p, 2);
    p += __shfl_xor_sync(0xffffffffu, p, 4);
    float cc2 = p + CSTF;
    float cc1 = g_Cc1[n * 4 + h];

    float hop0 = g_coef[0], tele = g_coef[1];
    float g1 = g_coef[2 + h], g2 = g_coef[6 + h];
    float hidden = g_V[n * 32 + l] * hop0
                 + g1 * g_Hh1[n * 32 + l] / cc1
                 + g2 * acc2 / cc2;

    const float invN = 1.0f / (float)NNODE;
    float num = 0.f, den = 0.f;
#pragma unroll
    for (int i = 0; i < 16; i++) {
        num += q[i] * g_TM[i * 32 + l];
        den += q[i] * g_TK[h * 16 + i];
    }
    float th = (num * invN) / (den * invN + CSTF);
    th += __shfl_xor_sync(0xffffffffu, th, 8);
    th += __shfl_xor_sync(0xffffffffu, th, 16);

    float wo[8];
#pragma unroll
    for (int c = 0; c < 8; c++) wo[c] = Wo[l * 8 + c];
    float res = 0.f;
#pragma unroll
    for (int c = 0; c < 8; c++) {
        float v = hidden * wo[c];
        v += __shfl_xor_sync(0xffffffffu, v, 16);
        v += __shfl_xor_sync(0xffffffffu, v, 8);
        v += __shfl_xor_sync(0xffffffffu, v, 4);
        v += __shfl_xor_sync(0xffffffffu, v, 2);
        v += __shfl_xor_sync(0xffffffffu, v, 1);
        if (l == c) res = v;
    }
    if (l < 8) out[n * 8 + l] = res + bo[l] + tele * th;
}

// ---------------- launch ---------------------------------------------------
extern "C" void kernel_launch(void* const* d_in, const int* in_sizes, int n_in,
                              void* d_out, int out_size) {
    const float*     feat = (const float*)d_in[0];
    const void*      ei   = d_in[1];
    const float*     Wi   = (const float*)d_in[2];
    const float*     bi   = (const float*)d_in[3];
    const float*     Wq   = (const float*)d_in[4];
    const float*     bq   = (const float*)d_in[5];
    const float*     Wk   = (const float*)d_in[6];
    const float*     bk   = (const float*)d_in[7];
    const float*     Wv   = (const float*)d_in[8];
    const float*     bv   = (const float*)d_in[9];
    const float*     Wo   = (const float*)d_in[10];
    const float*     bo   = (const float*)d_in[11];
    const float*     hopw = (const float*)d_in[12];
    const float*     headw= (const float*)d_in[13];
    const float*     tel  = (const float*)d_in[14];
    float* out = (float*)d_out;

    k_detect<<<1, 128>>>((const int*)ei);
    k_edges<<<(NEDGE + 255) / 256, 256>>>(ei);
    k_zero<<<(NNODE + 255) / 256, 256>>>();
    k_deg<<<(NEDGE + 255) / 256, 256>>>();
    k_scan<<<1, 1024>>>();
    k_scatter<<<(NEDGE + 255) / 256, 256>>>();
    k_coef<<<1, 32>>>(hopw, headw, tel);
    k_gemm_x<<<(NNODE + 127) / 128, 256>>>(feat, Wi, bi);
    k_qkv<<<(NNODE + 63) / 64, 256>>>(Wq, bq, Wk, bk, Wv, bv);
    k_tmtk<<<(NNODE + 63) / 64, 256>>>();
    k_hop1<<<(NNODE * 32 + 255) / 256, 256>>>();
    k_hop2<<<(NNODE * 32 + 255) / 256, 256>>>(Wo, bo, out);
}